// round 4
// baseline (speedup 1.0000x reference)
#include <cuda_runtime.h>
#include <cstddef>

// LSTM autoencoder, fused single kernel. B=256, T=4096, IN_DIM=1, HID=32, Z=16.
// One warp per batch element, one warp per SMSP (64 blocks x 128 threads).
// Encoder matvec uses Blackwell packed fma.rn.f32x2 with (even,odd) pair
// accumulation; h exchanged via double-buffered shared memory (1 STS + 8 LDS.128
// per step instead of 32 SHFL). Decoder uses exact fixed-point early exit.

#define FULL_MASK 0xFFFFFFFFu

namespace {
constexpr int Tt  = 4096;
constexpr int HID = 32;
constexpr int Zz  = 16;

__device__ __forceinline__ float sigf(float x) {
    return __fdividef(1.0f, 1.0f + __expf(-x));
}
__device__ __forceinline__ float tanh_fast(float x) {
    float ax = fabsf(x);
    float e  = __expf(-2.0f * ax);
    float t  = __fdividef(1.0f - e, 1.0f + e);
    return copysignf(t, x);
}

__device__ __forceinline__ unsigned long long pack2(float lo, float hi) {
    unsigned long long r;
    asm("mov.b64 %0, {%1, %2};" : "=l"(r) : "f"(lo), "f"(hi));
    return r;
}
__device__ __forceinline__ float2 unpack2(unsigned long long v) {
    float2 f;
    asm("mov.b64 {%0, %1}, %2;" : "=f"(f.x), "=f"(f.y) : "l"(v));
    return f;
}
__device__ __forceinline__ void ffma2(unsigned long long& acc,
                                      unsigned long long a,
                                      unsigned long long b) {
    asm("fma.rn.f32x2 %0, %1, %2, %0;" : "+l"(acc) : "l"(a), "l"(b));
}
} // namespace

__global__ __launch_bounds__(128, 1)
void lstm_ae_kernel(const float* __restrict__ x,
                    const float* __restrict__ enc_Wih,
                    const float* __restrict__ enc_Whh,
                    const float* __restrict__ enc_bih,
                    const float* __restrict__ enc_bhh,
                    const float* __restrict__ toz_W,
                    const float* __restrict__ toz_b,
                    const float* __restrict__ fromz_W,
                    const float* __restrict__ fromz_b,
                    const float* __restrict__ dec_Wih,
                    const float* __restrict__ dec_Whh,
                    const float* __restrict__ dec_bih,
                    const float* __restrict__ dec_bhh,
                    float* __restrict__ out)
{
    __shared__ __align__(16) float hbuf[4][2][HID];

    const int lane = threadIdx.x & 31;
    const int warp = threadIdx.x >> 5;
    const int b    = blockIdx.x * 4 + warp;   // 64 blocks x 4 warps = 256
    const int j    = lane;

    // ---- packed encoder recurrent weights: (even,odd) k pairs per gate ----
    unsigned long long wp0[HID/2], wp1[HID/2], wp2[HID/2], wp3[HID/2];
#pragma unroll
    for (int m = 0; m < HID / 2; ++m) {
        wp0[m] = pack2(enc_Whh[(j      ) * HID + 2*m], enc_Whh[(j      ) * HID + 2*m + 1]);
        wp1[m] = pack2(enc_Whh[(j + 32 ) * HID + 2*m], enc_Whh[(j + 32 ) * HID + 2*m + 1]);
        wp2[m] = pack2(enc_Whh[(j + 64 ) * HID + 2*m], enc_Whh[(j + 64 ) * HID + 2*m + 1]);
        wp3[m] = pack2(enc_Whh[(j + 96 ) * HID + 2*m], enc_Whh[(j + 96 ) * HID + 2*m + 1]);
    }
    const float a0 = enc_bih[j     ] + enc_bhh[j     ];
    const float a1 = enc_bih[j + 32] + enc_bhh[j + 32];
    const float a2 = enc_bih[j + 64] + enc_bhh[j + 64];
    const float a3 = enc_bih[j + 96] + enc_bhh[j + 96];
    const float wx0 = enc_Wih[j     ];
    const float wx1 = enc_Wih[j + 32];
    const float wx2 = enc_Wih[j + 64];
    const float wx3 = enc_Wih[j + 96];

    // ---- encoder recurrence ----
    float h = 0.0f, c = 0.0f;
    const float* xb = x + (size_t)b * Tt;

    for (int t0 = 0; t0 < Tt; t0 += 32) {
        float xv = xb[t0 + lane];                 // coalesced input prefetch
#pragma unroll 2
        for (int s = 0; s < 32; ++s) {
            hbuf[warp][s & 1][lane] = h;          // publish own h
            float xs = __shfl_sync(FULL_MASK, xv, s);
            // x-term + bias, folded into accumulator lo-half
            unsigned long long acc0 = pack2(fmaf(xs, wx0, a0), 0.0f);
            unsigned long long acc1 = pack2(fmaf(xs, wx1, a1), 0.0f);
            unsigned long long acc2 = pack2(fmaf(xs, wx2, a2), 0.0f);
            unsigned long long acc3 = pack2(fmaf(xs, wx3, a3), 0.0f);
            __syncwarp();
            const ulonglong2* hp =
                reinterpret_cast<const ulonglong2*>(hbuf[warp][s & 1]);
#pragma unroll
            for (int i = 0; i < HID / 4; ++i) {   // 8 x LDS.128 -> 16 pairs
                ulonglong2 q = hp[i];
                ffma2(acc0, wp0[2*i    ], q.x);
                ffma2(acc1, wp1[2*i    ], q.x);
                ffma2(acc2, wp2[2*i    ], q.x);
                ffma2(acc3, wp3[2*i    ], q.x);
                ffma2(acc0, wp0[2*i + 1], q.y);
                ffma2(acc1, wp1[2*i + 1], q.y);
                ffma2(acc2, wp2[2*i + 1], q.y);
                ffma2(acc3, wp3[2*i + 1], q.y);
            }
            float2 u0 = unpack2(acc0);
            float2 u1 = unpack2(acc1);
            float2 u2 = unpack2(acc2);
            float2 u3 = unpack2(acc3);
            float ig = sigf(u0.x + u0.y);
            float fg = sigf(u1.x + u1.y);
            float gu = tanh_fast(u2.x + u2.y);
            float og = sigf(u3.x + u3.y);
            c = fmaf(fg, c, ig * gu);
            h = og * tanh_fast(c);
        }
    }

    // ---- bottleneck projections ----
    float hv[HID];
#pragma unroll
    for (int k = 0; k < HID; ++k) hv[k] = __shfl_sync(FULL_MASK, h, k);

    float zv[Zz];
#pragma unroll
    for (int m = 0; m < Zz; ++m) {
        float acc = toz_b[m];
#pragma unroll
        for (int k = 0; k < HID; ++k) acc = fmaf(toz_W[m * HID + k], hv[k], acc);
        zv[m] = acc;
    }
    float acc0f = fromz_b[j];
#pragma unroll
    for (int m = 0; m < Zz; ++m) acc0f = fmaf(fromz_W[j * Zz + m], zv[m], acc0f);
    float h0 = tanh_fast(acc0f);

    float h0v[HID];
#pragma unroll
    for (int k = 0; k < HID; ++k) h0v[k] = __shfl_sync(FULL_MASK, h0, k);

    // ---- decoder: hidden dim 1, constant input over time ----
    float xg[4], wh[4];
#pragma unroll
    for (int g = 0; g < 4; ++g) {
        float a = dec_bih[g] + dec_bhh[g];
#pragma unroll
        for (int k = 0; k < HID; ++k) a = fmaf(dec_Wih[g * HID + k], h0v[k], a);
        xg[g] = a;
        wh[g] = dec_Whh[g];
    }

    float dh = 0.0f, dc = 0.0f, keep = 0.0f;
    float* ob = out + (size_t)b * Tt;

    int t0 = 0;
    for (; t0 < Tt; t0 += 32) {
        float sh = dh, sc = dc;                   // state at block start
#pragma unroll 1
        for (int s = 0; s < 32; ++s) {
            float gi = fmaf(wh[0], dh, xg[0]);
            float gf = fmaf(wh[1], dh, xg[1]);
            float gg = fmaf(wh[2], dh, xg[2]);
            float go = fmaf(wh[3], dh, xg[3]);
            float ig = sigf(gi);
            float fg = sigf(gf);
            float gu = tanh_fast(gg);
            float og = sigf(go);
            dc = fmaf(fg, dc, ig * gu);
            dh = og * tanh_fast(dc);
            if (lane == s) keep = dh;             // lane s archives step t0+s
        }
        ob[t0 + lane] = keep;                     // coalesced 128B store
        if (dh == sh && dc == sc) {               // exact fixed point / period
            t0 += 32;                             // deterministic map => all
            break;                                // later blocks repeat `keep`
        }
    }
    for (; t0 < Tt; t0 += 32) ob[t0 + lane] = keep;
}

extern "C" void kernel_launch(void* const* d_in, const int* in_sizes, int n_in,
                              void* d_out, int out_size)
{
    (void)in_sizes; (void)n_in; (void)out_size;
    const float* x        = (const float*)d_in[0];
    const float* enc_Wih  = (const float*)d_in[1];
    const float* enc_Whh  = (const float*)d_in[2];
    const float* enc_bih  = (const float*)d_in[3];
    const float* enc_bhh  = (const float*)d_in[4];
    const float* toz_W    = (const float*)d_in[5];
    const float* toz_b    = (const float*)d_in[6];
    const float* fromz_W  = (const float*)d_in[7];
    const float* fromz_b  = (const float*)d_in[8];
    const float* dec_Wih  = (const float*)d_in[9];
    const float* dec_Whh  = (const float*)d_in[10];
    const float* dec_bih  = (const float*)d_in[11];
    const float* dec_bhh  = (const float*)d_in[12];
    float* out = (float*)d_out;

    lstm_ae_kernel<<<64, 128>>>(x, enc_Wih, enc_Whh, enc_bih, enc_bhh,
                                toz_W, toz_b, fromz_W, fromz_b,
                                dec_Wih, dec_Whh, dec_bih, dec_bhh, out);
}

// round 5
// speedup vs baseline: 1.0086x; 1.0086x over previous
#include <cuda_runtime.h>
#include <cstddef>

// LSTM autoencoder, fused single kernel. B=256, T=4096, IN_DIM=1, HID=32, Z=16.
// One warp per batch element, one warp per SMSP (64 blocks x 128 threads).
// Encoder matvec: Blackwell packed fma.rn.f32x2, (even,odd)-pair accumulation,
// h exchanged via per-warp smem (1 STS + 8 LDS.128; relies on per-warp in-order
// MIO for the STS->LDS dependency, no syncwarp). Activations: HW tanh.approx
// with the sigmoid 0.5-prescale folded into weights/biases at setup.
// Decoder: hidden dim 1, constant input, exact fixed-point early exit.

#define FULL_MASK 0xFFFFFFFFu

namespace {
constexpr int Tt  = 4096;
constexpr int HID = 32;
constexpr int Zz  = 16;

__device__ __forceinline__ float tanhap(float x) {
    float y;
    asm("tanh.approx.f32 %0, %1;" : "=f"(y) : "f"(x));
    return y;
}
// Precise tanh, used only for once-per-batch bottleneck math.
__device__ __forceinline__ float tanh_exact(float x) {
    float ax = fabsf(x);
    float e  = __expf(-2.0f * ax);
    return copysignf(__fdividef(1.0f - e, 1.0f + e), x);
}
__device__ __forceinline__ unsigned long long pack2(float lo, float hi) {
    unsigned long long r;
    asm("mov.b64 %0, {%1, %2};" : "=l"(r) : "f"(lo), "f"(hi));
    return r;
}
__device__ __forceinline__ float2 unpack2(unsigned long long v) {
    float2 f;
    asm("mov.b64 {%0, %1}, %2;" : "=f"(f.x), "=f"(f.y) : "l"(v));
    return f;
}
__device__ __forceinline__ void ffma2(unsigned long long& acc,
                                      unsigned long long a,
                                      unsigned long long b) {
    asm("fma.rn.f32x2 %0, %1, %2, %0;" : "+l"(acc) : "l"(a), "l"(b));
}
} // namespace

__global__ __launch_bounds__(128, 1)
void lstm_ae_kernel(const float* __restrict__ x,
                    const float* __restrict__ enc_Wih,
                    const float* __restrict__ enc_Whh,
                    const float* __restrict__ enc_bih,
                    const float* __restrict__ enc_bhh,
                    const float* __restrict__ toz_W,
                    const float* __restrict__ toz_b,
                    const float* __restrict__ fromz_W,
                    const float* __restrict__ fromz_b,
                    const float* __restrict__ dec_Wih,
                    const float* __restrict__ dec_Whh,
                    const float* __restrict__ dec_bih,
                    const float* __restrict__ dec_bhh,
                    float* __restrict__ out)
{
    __shared__ __align__(16) float hbuf[4][2][HID];

    const int lane = threadIdx.x & 31;
    const int warp = threadIdx.x >> 5;
    const int b    = blockIdx.x * 4 + warp;   // 64 blocks x 4 warps = 256
    const int j    = lane;

    // ---- packed encoder recurrent weights, sigmoid gates (i,f,o) pre-scaled
    //      by 0.5 so sigmoid(x) = 0.5*tanh(0.5x)+0.5 costs one post-FMA ----
    unsigned long long wp0[HID/2], wp1[HID/2], wp2[HID/2], wp3[HID/2];
#pragma unroll
    for (int m = 0; m < HID / 2; ++m) {
        wp0[m] = pack2(0.5f * enc_Whh[(j      ) * HID + 2*m], 0.5f * enc_Whh[(j      ) * HID + 2*m + 1]);
        wp1[m] = pack2(0.5f * enc_Whh[(j + 32 ) * HID + 2*m], 0.5f * enc_Whh[(j + 32 ) * HID + 2*m + 1]);
        wp2[m] = pack2(       enc_Whh[(j + 64 ) * HID + 2*m],        enc_Whh[(j + 64 ) * HID + 2*m + 1]);
        wp3[m] = pack2(0.5f * enc_Whh[(j + 96 ) * HID + 2*m], 0.5f * enc_Whh[(j + 96 ) * HID + 2*m + 1]);
    }
    const float a0 = 0.5f * (enc_bih[j     ] + enc_bhh[j     ]);
    const float a1 = 0.5f * (enc_bih[j + 32] + enc_bhh[j + 32]);
    const float a2 =        (enc_bih[j + 64] + enc_bhh[j + 64]);
    const float a3 = 0.5f * (enc_bih[j + 96] + enc_bhh[j + 96]);
    const float wx0 = 0.5f * enc_Wih[j     ];
    const float wx1 = 0.5f * enc_Wih[j + 32];
    const float wx2 =        enc_Wih[j + 64];
    const float wx3 = 0.5f * enc_Wih[j + 96];

    // ---- encoder recurrence ----
    float h = 0.0f, c = 0.0f;
    const float* xb = x + (size_t)b * Tt;

    for (int t0 = 0; t0 < Tt; t0 += 32) {
        float xv = xb[t0 + lane];                 // coalesced input prefetch
#pragma unroll 2
        for (int s = 0; s < 32; ++s) {
            hbuf[warp][s & 1][lane] = h;          // publish own h (per-warp
                                                  // in-order MIO orders the
                                                  // LDS below behind this STS)
            float xs = __shfl_sync(FULL_MASK, xv, s);
            unsigned long long acc0 = pack2(fmaf(xs, wx0, a0), 0.0f);
            unsigned long long acc1 = pack2(fmaf(xs, wx1, a1), 0.0f);
            unsigned long long acc2 = pack2(fmaf(xs, wx2, a2), 0.0f);
            unsigned long long acc3 = pack2(fmaf(xs, wx3, a3), 0.0f);
            const ulonglong2* hp =
                reinterpret_cast<const ulonglong2*>(hbuf[warp][s & 1]);
#pragma unroll
            for (int i = 0; i < HID / 4; ++i) {   // 8 x LDS.128 -> 16 pairs
                ulonglong2 q = hp[i];
                ffma2(acc0, wp0[2*i    ], q.x);
                ffma2(acc1, wp1[2*i    ], q.x);
                ffma2(acc2, wp2[2*i    ], q.x);
                ffma2(acc3, wp3[2*i    ], q.x);
                ffma2(acc0, wp0[2*i + 1], q.y);
                ffma2(acc1, wp1[2*i + 1], q.y);
                ffma2(acc2, wp2[2*i + 1], q.y);
                ffma2(acc3, wp3[2*i + 1], q.y);
            }
            float2 u0 = unpack2(acc0);
            float2 u1 = unpack2(acc1);
            float2 u2 = unpack2(acc2);
            float2 u3 = unpack2(acc3);
            float ig = fmaf(tanhap(u0.x + u0.y), 0.5f, 0.5f);
            float fg = fmaf(tanhap(u1.x + u1.y), 0.5f, 0.5f);
            float gu =      tanhap(u2.x + u2.y);
            float og = fmaf(tanhap(u3.x + u3.y), 0.5f, 0.5f);
            c = fmaf(fg, c, ig * gu);
            h = og * tanhap(c);
        }
    }

    // ---- bottleneck projections (once per batch; precise math) ----
    float hv[HID];
#pragma unroll
    for (int k = 0; k < HID; ++k) hv[k] = __shfl_sync(FULL_MASK, h, k);

    float zv[Zz];
#pragma unroll
    for (int m = 0; m < Zz; ++m) {
        float acc = toz_b[m];
#pragma unroll
        for (int k = 0; k < HID; ++k) acc = fmaf(toz_W[m * HID + k], hv[k], acc);
        zv[m] = acc;
    }
    float acc0f = fromz_b[j];
#pragma unroll
    for (int m = 0; m < Zz; ++m) acc0f = fmaf(fromz_W[j * Zz + m], zv[m], acc0f);
    float h0 = tanh_exact(acc0f);

    float h0v[HID];
#pragma unroll
    for (int k = 0; k < HID; ++k) h0v[k] = __shfl_sync(FULL_MASK, h0, k);

    // ---- decoder: hidden dim 1, constant input; sigmoid gates pre-scaled ----
    float xg[4], wh[4];
#pragma unroll
    for (int g = 0; g < 4; ++g) {
        float a = dec_bih[g] + dec_bhh[g];
#pragma unroll
        for (int k = 0; k < HID; ++k) a = fmaf(dec_Wih[g * HID + k], h0v[k], a);
        float sc = (g == 2) ? 1.0f : 0.5f;
        xg[g] = sc * a;
        wh[g] = sc * dec_Whh[g];
    }

    float dh = 0.0f, dc = 0.0f, keep = 0.0f;
    float* ob = out + (size_t)b * Tt;

    int t0 = 0;
    for (; t0 < Tt; t0 += 32) {
        float sh = dh, sc0 = dc;                  // state at block start
#pragma unroll 1
        for (int s = 0; s < 32; ++s) {
            float ig = fmaf(tanhap(fmaf(wh[0], dh, xg[0])), 0.5f, 0.5f);
            float fg = fmaf(tanhap(fmaf(wh[1], dh, xg[1])), 0.5f, 0.5f);
            float gu =      tanhap(fmaf(wh[2], dh, xg[2]));
            float og = fmaf(tanhap(fmaf(wh[3], dh, xg[3])), 0.5f, 0.5f);
            dc = fmaf(fg, dc, ig * gu);
            dh = og * tanhap(dc);
            keep = (lane == s) ? dh : keep;       // lane s archives step t0+s
        }
        ob[t0 + lane] = keep;                     // coalesced 128B store
        if (dh == sh && dc == sc0) {              // exact fixed point/period:
            t0 += 32;                             // deterministic map => all
            break;                                // later blocks repeat `keep`
        }
    }
    for (; t0 < Tt; t0 += 32) ob[t0 + lane] = keep;
}

extern "C" void kernel_launch(void* const* d_in, const int* in_sizes, int n_in,
                              void* d_out, int out_size)
{
    (void)in_sizes; (void)n_in; (void)out_size;
    const float* x        = (const float*)d_in[0];
    const float* enc_Wih  = (const float*)d_in[1];
    const float* enc_Whh  = (const float*)d_in[2];
    const float* enc_bih  = (const float*)d_in[3];
    const float* enc_bhh  = (const float*)d_in[4];
    const float* toz_W    = (const float*)d_in[5];
    const float* toz_b    = (const float*)d_in[6];
    const float* fromz_W  = (const float*)d_in[7];
    const float* fromz_b  = (const float*)d_in[8];
    const float* dec_Wih  = (const float*)d_in[9];
    const float* dec_Whh  = (const float*)d_in[10];
    const float* dec_bih  = (const float*)d_in[11];
    const float* dec_bhh  = (const float*)d_in[12];
    float* out = (float*)d_out;

    lstm_ae_kernel<<<64, 128>>>(x, enc_Wih, enc_Whh, enc_bih, enc_bhh,
                                toz_W, toz_b, fromz_W, fromz_b,
                                dec_Wih, dec_Whh, dec_bih, dec_bhh, out);
}

// round 6
// speedup vs baseline: 1.0203x; 1.0116x over previous
#include <cuda_runtime.h>
#include <cstddef>

// LSTM autoencoder, fused single kernel. B=256, T=4096, IN_DIM=1, HID=32, Z=16.
// One warp per batch element, one warp per SMSP (64 blocks x 128 threads).
// Encoder matvec: Blackwell packed fma.rn.f32x2, (even,odd)-pair accumulation,
// h exchanged via per-warp smem (1 STS + 8 LDS.128; relies on per-warp in-order
// MIO for the STS->LDS dependency, no syncwarp). Activations: HW tanh.approx
// with the sigmoid 0.5-prescale folded into weights/biases at setup.
// Decoder: hidden dim 1, constant input, exact fixed-point early exit.

#define FULL_MASK 0xFFFFFFFFu

namespace {
constexpr int Tt  = 4096;
constexpr int HID = 32;
constexpr int Zz  = 16;

__device__ __forceinline__ float tanhap(float x) {
    float y;
    asm("tanh.approx.f32 %0, %1;" : "=f"(y) : "f"(x));
    return y;
}
// Precise tanh, used only for once-per-batch bottleneck math.
__device__ __forceinline__ float tanh_exact(float x) {
    float ax = fabsf(x);
    float e  = __expf(-2.0f * ax);
    return copysignf(__fdividef(1.0f - e, 1.0f + e), x);
}
__device__ __forceinline__ unsigned long long pack2(float lo, float hi) {
    unsigned long long r;
    asm("mov.b64 %0, {%1, %2};" : "=l"(r) : "f"(lo), "f"(hi));
    return r;
}
__device__ __forceinline__ float2 unpack2(unsigned long long v) {
    float2 f;
    asm("mov.b64 {%0, %1}, %2;" : "=f"(f.x), "=f"(f.y) : "l"(v));
    return f;
}
__device__ __forceinline__ void ffma2(unsigned long long& acc,
                                      unsigned long long a,
                                      unsigned long long b) {
    asm("fma.rn.f32x2 %0, %1, %2, %0;" : "+l"(acc) : "l"(a), "l"(b));
}
} // namespace

__global__ __launch_bounds__(128, 1)
void lstm_ae_kernel(const float* __restrict__ x,
                    const float* __restrict__ enc_Wih,
                    const float* __restrict__ enc_Whh,
                    const float* __restrict__ enc_bih,
                    const float* __restrict__ enc_bhh,
                    const float* __restrict__ toz_W,
                    const float* __restrict__ toz_b,
                    const float* __restrict__ fromz_W,
                    const float* __restrict__ fromz_b,
                    const float* __restrict__ dec_Wih,
                    const float* __restrict__ dec_Whh,
                    const float* __restrict__ dec_bih,
                    const float* __restrict__ dec_bhh,
                    float* __restrict__ out)
{
    __shared__ __align__(16) float hbuf[4][2][HID];

    const int lane = threadIdx.x & 31;
    const int warp = threadIdx.x >> 5;
    const int b    = blockIdx.x * 4 + warp;   // 64 blocks x 4 warps = 256
    const int j    = lane;

    // ---- packed encoder recurrent weights, sigmoid gates (i,f,o) pre-scaled
    //      by 0.5 so sigmoid(x) = 0.5*tanh(0.5x)+0.5 costs one post-FMA ----
    unsigned long long wp0[HID/2], wp1[HID/2], wp2[HID/2], wp3[HID/2];
#pragma unroll
    for (int m = 0; m < HID / 2; ++m) {
        wp0[m] = pack2(0.5f * enc_Whh[(j      ) * HID + 2*m], 0.5f * enc_Whh[(j      ) * HID + 2*m + 1]);
        wp1[m] = pack2(0.5f * enc_Whh[(j + 32 ) * HID + 2*m], 0.5f * enc_Whh[(j + 32 ) * HID + 2*m + 1]);
        wp2[m] = pack2(       enc_Whh[(j + 64 ) * HID + 2*m],        enc_Whh[(j + 64 ) * HID + 2*m + 1]);
        wp3[m] = pack2(0.5f * enc_Whh[(j + 96 ) * HID + 2*m], 0.5f * enc_Whh[(j + 96 ) * HID + 2*m + 1]);
    }
    const float a0 = 0.5f * (enc_bih[j     ] + enc_bhh[j     ]);
    const float a1 = 0.5f * (enc_bih[j + 32] + enc_bhh[j + 32]);
    const float a2 =        (enc_bih[j + 64] + enc_bhh[j + 64]);
    const float a3 = 0.5f * (enc_bih[j + 96] + enc_bhh[j + 96]);
    const float wx0 = 0.5f * enc_Wih[j     ];
    const float wx1 = 0.5f * enc_Wih[j + 32];
    const float wx2 =        enc_Wih[j + 64];
    const float wx3 = 0.5f * enc_Wih[j + 96];

    // ---- encoder recurrence ----
    float h = 0.0f, c = 0.0f;
    const float* xb = x + (size_t)b * Tt;

    for (int t0 = 0; t0 < Tt; t0 += 32) {
        float xv = xb[t0 + lane];                 // coalesced input prefetch
#pragma unroll 2
        for (int s = 0; s < 32; ++s) {
            hbuf[warp][s & 1][lane] = h;          // publish own h (per-warp
                                                  // in-order MIO orders the
                                                  // LDS below behind this STS)
            float xs = __shfl_sync(FULL_MASK, xv, s);
            unsigned long long acc0 = pack2(fmaf(xs, wx0, a0), 0.0f);
            unsigned long long acc1 = pack2(fmaf(xs, wx1, a1), 0.0f);
            unsigned long long acc2 = pack2(fmaf(xs, wx2, a2), 0.0f);
            unsigned long long acc3 = pack2(fmaf(xs, wx3, a3), 0.0f);
            const ulonglong2* hp =
                reinterpret_cast<const ulonglong2*>(hbuf[warp][s & 1]);
#pragma unroll
            for (int i = 0; i < HID / 4; ++i) {   // 8 x LDS.128 -> 16 pairs
                ulonglong2 q = hp[i];
                ffma2(acc0, wp0[2*i    ], q.x);
                ffma2(acc1, wp1[2*i    ], q.x);
                ffma2(acc2, wp2[2*i    ], q.x);
                ffma2(acc3, wp3[2*i    ], q.x);
                ffma2(acc0, wp0[2*i + 1], q.y);
                ffma2(acc1, wp1[2*i + 1], q.y);
                ffma2(acc2, wp2[2*i + 1], q.y);
                ffma2(acc3, wp3[2*i + 1], q.y);
            }
            float2 u0 = unpack2(acc0);
            float2 u1 = unpack2(acc1);
            float2 u2 = unpack2(acc2);
            float2 u3 = unpack2(acc3);
            float ig = fmaf(tanhap(u0.x + u0.y), 0.5f, 0.5f);
            float fg = fmaf(tanhap(u1.x + u1.y), 0.5f, 0.5f);
            float gu =      tanhap(u2.x + u2.y);
            float og = fmaf(tanhap(u3.x + u3.y), 0.5f, 0.5f);
            c = fmaf(fg, c, ig * gu);
            h = og * tanhap(c);
        }
    }

    // ---- bottleneck projections (once per batch; precise math) ----
    float hv[HID];
#pragma unroll
    for (int k = 0; k < HID; ++k) hv[k] = __shfl_sync(FULL_MASK, h, k);

    float zv[Zz];
#pragma unroll
    for (int m = 0; m < Zz; ++m) {
        float acc = toz_b[m];
#pragma unroll
        for (int k = 0; k < HID; ++k) acc = fmaf(toz_W[m * HID + k], hv[k], acc);
        zv[m] = acc;
    }
    float acc0f = fromz_b[j];
#pragma unroll
    for (int m = 0; m < Zz; ++m) acc0f = fmaf(fromz_W[j * Zz + m], zv[m], acc0f);
    float h0 = tanh_exact(acc0f);

    float h0v[HID];
#pragma unroll
    for (int k = 0; k < HID; ++k) h0v[k] = __shfl_sync(FULL_MASK, h0, k);

    // ---- decoder: hidden dim 1, constant input; sigmoid gates pre-scaled ----
    float xg[4], wh[4];
#pragma unroll
    for (int g = 0; g < 4; ++g) {
        float a = dec_bih[g] + dec_bhh[g];
#pragma unroll
        for (int k = 0; k < HID; ++k) a = fmaf(dec_Wih[g * HID + k], h0v[k], a);
        float sc = (g == 2) ? 1.0f : 0.5f;
        xg[g] = sc * a;
        wh[g] = sc * dec_Whh[g];
    }

    float dh = 0.0f, dc = 0.0f, keep = 0.0f;
    float* ob = out + (size_t)b * Tt;

    int t0 = 0;
    for (; t0 < Tt; t0 += 32) {
        float sh = dh, sc0 = dc;                  // state at block start
#pragma unroll 1
        for (int s = 0; s < 32; ++s) {
            float ig = fmaf(tanhap(fmaf(wh[0], dh, xg[0])), 0.5f, 0.5f);
            float fg = fmaf(tanhap(fmaf(wh[1], dh, xg[1])), 0.5f, 0.5f);
            float gu =      tanhap(fmaf(wh[2], dh, xg[2]));
            float og = fmaf(tanhap(fmaf(wh[3], dh, xg[3])), 0.5f, 0.5f);
            dc = fmaf(fg, dc, ig * gu);
            dh = og * tanhap(dc);
            keep = (lane == s) ? dh : keep;       // lane s archives step t0+s
        }
        ob[t0 + lane] = keep;                     // coalesced 128B store
        if (dh == sh && dc == sc0) {              // exact fixed point/period:
            t0 += 32;                             // deterministic map => all
            break;                                // later blocks repeat `keep`
        }
    }
    for (; t0 < Tt; t0 += 32) ob[t0 + lane] = keep;
}

extern "C" void kernel_launch(void* const* d_in, const int* in_sizes, int n_in,
                              void* d_out, int out_size)
{
    (void)in_sizes; (void)n_in; (void)out_size;
    const float* x        = (const float*)d_in[0];
    const float* enc_Wih  = (const float*)d_in[1];
    const float* enc_Whh  = (const float*)d_in[2];
    const float* enc_bih  = (const float*)d_in[3];
    const float* enc_bhh  = (const float*)d_in[4];
    const float* toz_W    = (const float*)d_in[5];
    const float* toz_b    = (const float*)d_in[6];
    const float* fromz_W  = (const float*)d_in[7];
    const float* fromz_b  = (const float*)d_in[8];
    const float* dec_Wih  = (const float*)d_in[9];
    const float* dec_Whh  = (const float*)d_in[10];
    const float* dec_bih  = (const float*)d_in[11];
    const float* dec_bhh  = (const float*)d_in[12];
    float* out = (float*)d_out;

    lstm_ae_kernel<<<64, 128>>>(x, enc_Wih, enc_Whh, enc_bih, enc_bhh,
                                toz_W, toz_b, fromz_W, fromz_b,
                                dec_Wih, dec_Whh, dec_bih, dec_bhh, out);
}